// round 2
// baseline (speedup 1.0000x reference)
#include <cuda_runtime.h>
#include <cstdint>

// out[b,a,f] = relu(features[b,a,f] + residuals[0,b,a,f] + residuals[1,b,a,f])
//              if a < n_atoms[b] else 0
// B=256, A=128, F=1024, N_RES=2, fp32.

#define BATCH 256
#define MAX_ATOM 128
#define N_FEAT 1024
#define F4_PER_ROW (N_FEAT / 4)                    // 256
#define TENSOR_F4 (BATCH * MAX_ATOM * F4_PER_ROW)  // 8,388,608 float4 per tensor

__global__ __launch_bounds__(256, 8)
void dense_block_end_kernel(const float4* __restrict__ feat,
                            const float4* __restrict__ res,   // [2, B, A, F]
                            const int*    __restrict__ ms,    // mol_slice raw (int32 view)
                            float4* __restrict__ out) {
    const int row = blockIdx.x;          // b * MAX_ATOM + a
    const int b = row >> 7;              // / 128
    const int a = row & 127;

    // mol_slice layout detection (int32 vs int64 little-endian):
    //  int32 layout: [n0, 1024, n1, 1024, ...]        -> ms[1] == 1024
    //  int64 layout: [n0_lo, 0, 1024_lo, 0, n1_lo,..] -> ms[1] == 0
    const bool is_i32 = (__ldg(&ms[1]) == N_FEAT);
    const int n_atoms = __ldg(&ms[is_i32 ? (2 * b) : (4 * b)]);

    const size_t idx = (size_t)row * F4_PER_ROW + threadIdx.x;

    if (a >= n_atoms) {
        out[idx] = make_float4(0.f, 0.f, 0.f, 0.f);
        return;
    }

    const float4 f  = feat[idx];
    const float4 r0 = res[idx];
    const float4 r1 = res[idx + (size_t)TENSOR_F4];

    float4 o;
    o.x = fmaxf(f.x + r0.x + r1.x, 0.f);
    o.y = fmaxf(f.y + r0.y + r1.y, 0.f);
    o.z = fmaxf(f.z + r0.z + r1.z, 0.f);
    o.w = fmaxf(f.w + r0.w + r1.w, 0.f);
    out[idx] = o;
}

extern "C" void kernel_launch(void* const* d_in, const int* in_sizes, int n_in,
                              void* d_out, int out_size) {
    const float4* feat = (const float4*)d_in[0];
    const float4* res  = (const float4*)d_in[1];
    const int*    ms   = (const int*)d_in[2];
    float4* out = (float4*)d_out;

    dim3 grid(BATCH * MAX_ATOM);   // 32768 blocks, one per (b,a) row
    dim3 block(F4_PER_ROW);        // 256 threads, one float4 each
    dense_block_end_kernel<<<grid, block>>>(feat, res, ms, out);
}